// round 13
// baseline (speedup 1.0000x reference)
#include <cuda_runtime.h>
#include <math.h>

#define IMG_H 200
#define IMG_W 200
#define IMG_C 256
#define PIX_BYTES (IMG_C * 4)   // 1024 bytes per pixel
#define MAX_PP 64               // supports ps up to 8

struct CellGeom {
    unsigned o00, o01, o10, o11;  // BYTE offsets of the 4 corner pixels
    float wx, wy;
};

// 256-bit global accesses (Blackwell LDG.E.256 / STG.E.256): each lane owns
// 32 contiguous bytes, so one warp instruction covers a full 1KB pixel.
// Per cell: 4 LDG.256 + 1 STG.256 (vs 8 LDG.128 + 2 STG.128) — same bytes,
// same wavefronts, half the memory instructions / scoreboard traffic.
__device__ __forceinline__ void ldg256(const char* p, float4& lo, float4& hi) {
    asm("ld.global.nc.v8.f32 {%0,%1,%2,%3,%4,%5,%6,%7}, [%8];"
        : "=f"(lo.x), "=f"(lo.y), "=f"(lo.z), "=f"(lo.w),
          "=f"(hi.x), "=f"(hi.y), "=f"(hi.z), "=f"(hi.w)
        : "l"(p));
}
__device__ __forceinline__ void stg256(char* p, const float4& lo, const float4& hi) {
    asm volatile("st.global.v8.f32 [%0], {%1,%2,%3,%4,%5,%6,%7,%8};"
        :: "l"(p),
           "f"(lo.x), "f"(lo.y), "f"(lo.z), "f"(lo.w),
           "f"(hi.x), "f"(hi.y), "f"(hi.z), "f"(hi.w)
        : "memory");
}

#define BLEND2(ra, rb, wA, a0, b0, wB, a1, b1)                 \
    do {                                                       \
        (ra).x = (wA)*(a0).x + (wB)*(a1).x;                    \
        (ra).y = (wA)*(a0).y + (wB)*(a1).y;                    \
        (ra).z = (wA)*(a0).z + (wB)*(a1).z;                    \
        (ra).w = (wA)*(a0).w + (wB)*(a1).w;                    \
        (rb).x = (wA)*(b0).x + (wB)*(b1).x;                    \
        (rb).y = (wA)*(b0).y + (wB)*(b1).y;                    \
        (rb).z = (wA)*(b0).z + (wB)*(b1).z;                    \
        (rb).w = (wA)*(b0).w + (wB)*(b1).w;                    \
    } while (0)

__global__ __launch_bounds__(256, 5) void roipool_kernel(
        const float* __restrict__ img,
        const float* __restrict__ rois,
        float* __restrict__ out,
        int ps) {
    __shared__ CellGeom geom[MAX_PP];

    const int r    = blockIdx.x;
    const int warp = threadIdx.x >> 5;
    const int lane = threadIdx.x & 31;
    const int pp   = ps * ps;

    const float4 rv = reinterpret_cast<const float4*>(rois)[r];
    const int x = (int)rv.x;
    const int y = (int)rv.y;
    const int w = (int)rv.z;
    const int h = (int)rv.w;

    if (threadIdx.x < pp) {
        const int cell = threadIdx.x;
        const int py = cell / ps;
        const int px = cell - py * ps;

        const float sy = (float)h / (float)ps;
        const float sx = (float)w / (float)ps;
        const float src_y = (float)py * sy;
        const float src_x = (float)px * sx;
        const int y0 = (int)floorf(src_y);
        const int x0 = (int)floorf(src_x);

        const int gy0 = min(max(y + min(max(y0,     0), h - 1), 0), IMG_H - 1);
        const int gy1 = min(max(y + min(max(y0 + 1, 0), h - 1), 0), IMG_H - 1);
        const int gx0 = min(max(x + min(max(x0,     0), w - 1), 0), IMG_W - 1);
        const int gx1 = min(max(x + min(max(x0 + 1, 0), w - 1), 0), IMG_W - 1);

        CellGeom g;
        g.o00 = (unsigned)(gy0 * IMG_W + gx0) * PIX_BYTES;
        g.o01 = (unsigned)(gy0 * IMG_W + gx1) * PIX_BYTES;
        g.o10 = (unsigned)(gy1 * IMG_W + gx0) * PIX_BYTES;
        g.o11 = (unsigned)(gy1 * IMG_W + gx1) * PIX_BYTES;
        g.wx  = src_x - (float)x0;
        g.wy  = src_y - (float)y0;
        geom[cell] = g;
    }
    __syncthreads();

    // Each lane owns 32 contiguous bytes of the 1KB pixel.
    const unsigned co = (unsigned)lane * 32u;
    const char* __restrict__ ib = reinterpret_cast<const char*>(img) + co;
    char* __restrict__ ob = reinterpret_cast<char*>(out)
                          + (unsigned)r * (unsigned)pp * PIX_BYTES + co;

    for (int cell = warp; cell < pp; cell += 8) {
        const CellGeom g = geom[cell];          // broadcast LDS
        char* oc = ob + (unsigned)cell * PIX_BYTES;

        const float wx = g.wx, wy = g.wy;
        const bool zx = (wx == 0.0f);
        const bool zy = (wy == 0.0f);

        float4 ra, rb;

        if (zx && zy) {
            ldg256(ib + g.o00, ra, rb);
        } else if (zx) {
            float4 a0, b0, a1, b1;
            ldg256(ib + g.o00, a0, b0);
            ldg256(ib + g.o10, a1, b1);
            const float omwy = 1.0f - wy;
            BLEND2(ra, rb, omwy, a0, b0, wy, a1, b1);
        } else if (zy) {
            float4 a0, b0, a1, b1;
            ldg256(ib + g.o00, a0, b0);
            ldg256(ib + g.o01, a1, b1);
            const float omwx = 1.0f - wx;
            BLEND2(ra, rb, omwx, a0, b0, wx, a1, b1);
        } else {
            float4 a00, b00, a01, b01, a10, b10, a11, b11;
            ldg256(ib + g.o00, a00, b00);
            ldg256(ib + g.o01, a01, b01);
            ldg256(ib + g.o10, a10, b10);
            ldg256(ib + g.o11, a11, b11);

            const float omwx = 1.0f - wx;
            const float omwy = 1.0f - wy;
            const float w00 = omwx * omwy;
            const float w01 = wx * omwy;
            const float w10 = omwx * wy;
            const float w11 = wx * wy;

            ra.x = w00*a00.x + w01*a01.x + w10*a10.x + w11*a11.x;
            ra.y = w00*a00.y + w01*a01.y + w10*a10.y + w11*a11.y;
            ra.z = w00*a00.z + w01*a01.z + w10*a10.z + w11*a11.z;
            ra.w = w00*a00.w + w01*a01.w + w10*a10.w + w11*a11.w;
            rb.x = w00*b00.x + w01*b01.x + w10*b10.x + w11*b11.x;
            rb.y = w00*b00.y + w01*b01.y + w10*b10.y + w11*b11.y;
            rb.z = w00*b00.z + w01*b01.z + w10*b10.z + w11*b11.z;
            rb.w = w00*b00.w + w01*b01.w + w10*b10.w + w11*b11.w;
        }

        stg256(oc, ra, rb);
    }
}

extern "C" void kernel_launch(void* const* d_in, const int* in_sizes, int n_in,
                              void* d_out, int out_size) {
    const float* img  = (const float*)d_in[0];
    const float* rois = (const float*)d_in[1];
    float* out = (float*)d_out;

    const int n_rois = in_sizes[1] / 4;
    const int pp = out_size / (n_rois * IMG_C);
    int ps = (int)(sqrtf((float)pp) + 0.5f);
    if (ps < 1) ps = 1;
    if (ps * ps > MAX_PP) ps = 8;

    roipool_kernel<<<n_rois, 256>>>(img, rois, out, ps);
}